// round 8
// baseline (speedup 1.0000x reference)
#include <cuda_runtime.h>
#include <cuda_bf16.h>
#include <cstdint>

#define BB 2
#define TT 2048
#define CC 2048
#define HH 16
#define DD 128
#define MTOT (BB * TT)   // 4096
#define KTOT CC          // all GEMMs have K = 2048
#define NQKV 2304        // fused QKV output width: 2048 + 128 + 128
// 1/sqrt(128) * log2(e): softmax done in base-2
#define QSCALE (0.08838834764831845f * 1.44269504088896340f)

typedef __nv_bfloat16 bf16;

// ---------------------------------------------------------------------------
// Scratch (allocation-free: __device__ globals)
// ---------------------------------------------------------------------------
__device__ bf16 g_xh[(size_t)MTOT * CC],  g_xl[(size_t)MTOT * CC];
__device__ bf16 g_wh[(size_t)KTOT * NQKV], g_wl[(size_t)KTOT * NQKV];  // packed QKV W
__device__ bf16 g_woh[(size_t)CC * CC],   g_wol[(size_t)CC * CC];
__device__ float g_bias[NQKV];

__device__ bf16 g_Qh[(size_t)MTOT * CC],  g_Ql[(size_t)MTOT * CC];  // [B,H,T,D]
__device__ bf16 g_Kh[(size_t)MTOT * DD],  g_Kl[(size_t)MTOT * DD];  // [B,T,D]
__device__ bf16 g_Vh[(size_t)MTOT * DD],  g_Vl[(size_t)MTOT * DD];  // [B,T,D]
__device__ bf16 g_Oh[(size_t)MTOT * CC],  g_Ol[(size_t)MTOT * CC];  // [B,T,H*D]

// ---------------------------------------------------------------------------
// PTX helpers
// ---------------------------------------------------------------------------
__device__ __forceinline__ uint32_t smem_u32(const void* p) {
    uint32_t a;
    asm("{ .reg .u64 t; cvta.to.shared.u64 t, %1; cvt.u32.u64 %0, t; }"
        : "=r"(a) : "l"(p));
    return a;
}
__device__ __forceinline__ float ex2(float x) {
    float y;
    asm("ex2.approx.ftz.f32 %0, %1;" : "=f"(y) : "f"(x));
    return y;
}

#define LDSM_X4(r0, r1, r2, r3, addr) \
    asm volatile("ldmatrix.sync.aligned.m8n8.x4.shared.b16 {%0,%1,%2,%3}, [%4];" \
                 : "=r"(r0), "=r"(r1), "=r"(r2), "=r"(r3) : "r"(addr))
#define LDSM_X4_T(r0, r1, r2, r3, addr) \
    asm volatile("ldmatrix.sync.aligned.m8n8.x4.trans.shared.b16 {%0,%1,%2,%3}, [%4];" \
                 : "=r"(r0), "=r"(r1), "=r"(r2), "=r"(r3) : "r"(addr))

#define MMA_BF16(d, a, b0v, b1v) \
    asm volatile("mma.sync.aligned.m16n8k16.row.col.f32.bf16.bf16.f32 " \
                 "{%0,%1,%2,%3}, {%4,%5,%6,%7}, {%8,%9}, {%0,%1,%2,%3};" \
                 : "+f"((d)[0]), "+f"((d)[1]), "+f"((d)[2]), "+f"((d)[3]) \
                 : "r"((a)[0]), "r"((a)[1]), "r"((a)[2]), "r"((a)[3]), \
                   "r"(b0v), "r"(b1v))

#define CP16(dst, src) \
    asm volatile("cp.async.cg.shared.global [%0], [%1], 16;" :: "r"(dst), "l"(src))
#define CP_COMMIT() asm volatile("cp.async.commit_group;" ::: "memory")
#define CP_WAIT(n)  asm volatile("cp.async.wait_group %0;" :: "n"(n) : "memory")

__device__ __forceinline__ uint32_t pack_bf2(bf16 a, bf16 b) {
    return ((uint32_t)__bfloat16_as_ushort(b) << 16) | (uint32_t)__bfloat16_as_ushort(a);
}
__device__ __forceinline__ void split2(float x, float y, uint32_t& hi, uint32_t& lo) {
    bf16 hx = __float2bfloat16(x), hy = __float2bfloat16(y);
    hi = pack_bf2(hx, hy);
    lo = pack_bf2(__float2bfloat16(x - __bfloat162float(hx)),
                  __float2bfloat16(y - __bfloat162float(hy)));
}

// ---------------------------------------------------------------------------
// One merged prep kernel: all fp32->bf16 hi/lo splits + bias pack.
// ---------------------------------------------------------------------------
__global__ __launch_bounds__(256) void prep_kernel(
    const float* __restrict__ x,  const float* __restrict__ wq,
    const float* __restrict__ wk, const float* __restrict__ wv,
    const float* __restrict__ wo,
    const float* __restrict__ qb, const float* __restrict__ kb,
    const float* __restrict__ vb,
    bf16* __restrict__ xh, bf16* __restrict__ xl,
    bf16* __restrict__ wh, bf16* __restrict__ wl,
    bf16* __restrict__ woh, bf16* __restrict__ wol,
    float* __restrict__ bias)
{
    int blk = blockIdx.x;
    int tid = threadIdx.x;
    if (blk < 8192) {                     // x: contiguous
        int i = blk * 256 + tid;
        float4 v = ((const float4*)x)[i];
        uint32_t h0, l0, h1, l1;
        split2(v.x, v.y, h0, l0);
        split2(v.z, v.w, h1, l1);
        ((uint2*)xh)[i] = make_uint2(h0, h1);
        ((uint2*)xl)[i] = make_uint2(l0, l1);
    } else if (blk < 12288) {             // wq -> cols 0..2047
        int i = (blk - 8192) * 256 + tid;
        int row = i >> 9, col = (i << 2) & 2047;
        float4 v = ((const float4*)wq)[i];
        uint32_t h0, l0, h1, l1;
        split2(v.x, v.y, h0, l0);
        split2(v.z, v.w, h1, l1);
        size_t o = (size_t)row * NQKV + col;
        *(uint2*)(wh + o) = make_uint2(h0, h1);
        *(uint2*)(wl + o) = make_uint2(l0, l1);
    } else if (blk < 12544) {             // wk -> cols 2048..2175
        int i = (blk - 12288) * 256 + tid;
        int row = i >> 5, col = (i << 2) & 127;
        float4 v = ((const float4*)wk)[i];
        uint32_t h0, l0, h1, l1;
        split2(v.x, v.y, h0, l0);
        split2(v.z, v.w, h1, l1);
        size_t o = (size_t)row * NQKV + 2048 + col;
        *(uint2*)(wh + o) = make_uint2(h0, h1);
        *(uint2*)(wl + o) = make_uint2(l0, l1);
    } else if (blk < 12800) {             // wv -> cols 2176..2303
        int i = (blk - 12544) * 256 + tid;
        int row = i >> 5, col = (i << 2) & 127;
        float4 v = ((const float4*)wv)[i];
        uint32_t h0, l0, h1, l1;
        split2(v.x, v.y, h0, l0);
        split2(v.z, v.w, h1, l1);
        size_t o = (size_t)row * NQKV + 2176 + col;
        *(uint2*)(wh + o) = make_uint2(h0, h1);
        *(uint2*)(wl + o) = make_uint2(l0, l1);
    } else if (blk < 16896) {             // wo: contiguous
        int i = (blk - 12800) * 256 + tid;
        float4 v = ((const float4*)wo)[i];
        uint32_t h0, l0, h1, l1;
        split2(v.x, v.y, h0, l0);
        split2(v.z, v.w, h1, l1);
        ((uint2*)woh)[i] = make_uint2(h0, h1);
        ((uint2*)wol)[i] = make_uint2(l0, l1);
    } else {                              // bias pack
        int i = (blk - 16896) * 256 + tid;
        if (i < 2048)      bias[i] = qb[i];
        else if (i < 2176) bias[i] = kb[i - 2048];
        else if (i < 2304) bias[i] = vb[i - 2176];
    }
}

// ---------------------------------------------------------------------------
// Shared GEMM tile machinery: BM=128 BN=128 BK=32, 256 thr, cp.async 3-stage.
// ---------------------------------------------------------------------------
#define STG_BYTES 32768
#define G2SMEM (3 * STG_BYTES)
#define NITER (KTOT / 32)   // 64

__device__ __forceinline__ uint32_t a_off(int r, int c) {
    return (uint32_t)(r * 64 + ((c ^ ((r >> 1) & 3)) << 4));
}
__device__ __forceinline__ uint32_t b_off(int r, int c) {
    return (uint32_t)(r * 256 + ((c ^ (r & 7)) << 4));
}

__device__ __forceinline__ void g2s_issue(
    uint32_t stg, const bf16* __restrict__ Ah, const bf16* __restrict__ Al,
    const bf16* __restrict__ Wh, const bf16* __restrict__ Wl,
    int N, int m0, int n0, int k0, int tid)
{
#pragma unroll
    for (int p = 0; p < 2; p++) {
        int cid = p * 256 + tid;
        int r = cid >> 2, c = cid & 3;
        size_t gs = (size_t)(m0 + r) * KTOT + k0 + c * 8;
        uint32_t off = a_off(r, c);
        CP16(stg + off, Ah + gs);
        CP16(stg + 8192 + off, Al + gs);
    }
#pragma unroll
    for (int p = 0; p < 2; p++) {
        int cid = p * 256 + tid;
        int r = cid >> 4, c = cid & 15;
        size_t gs = (size_t)(k0 + r) * N + n0 + c * 8;
        uint32_t off = b_off(r, c);
        CP16(stg + 16384 + off, Wh + gs);
        CP16(stg + 24576 + off, Wl + gs);
    }
}

// Mainloop with term-major MMA ordering (RAW reuse distance 4 per acc frag).
__device__ __forceinline__ void gemm_mainloop(
    uint32_t sb, const bf16* Ah, const bf16* Al, const bf16* Wh, const bf16* Wl,
    int N, int m0, int n0, int tid, int lane, int wm, int wn, float acc[2][8][4])
{
    const int lrow = lane & 15;
    const int lsel = lane >> 4;

    g2s_issue(sb, Ah, Al, Wh, Wl, N, m0, n0, 0, tid);
    CP_COMMIT();
    g2s_issue(sb + STG_BYTES, Ah, Al, Wh, Wl, N, m0, n0, 32, tid);
    CP_COMMIT();

    for (int it = 0; it < NITER; it++) {
        if (it == NITER - 1) CP_WAIT(0); else CP_WAIT(1);
        __syncthreads();
        if (it + 2 < NITER) {
            g2s_issue(sb + ((it + 2) % 3) * STG_BYTES, Ah, Al, Wh, Wl, N,
                      m0, n0, (it + 2) * 32, tid);
            CP_COMMIT();
        }

        const uint32_t stA = sb + (uint32_t)(it % 3) * STG_BYTES;
        const uint32_t stB = stA + 16384;

#pragma unroll
        for (int ks = 0; ks < 2; ks++) {
            uint32_t ah[2][4], al[2][4];
#pragma unroll
            for (int mf = 0; mf < 2; mf++) {
                int row = wm * 32 + mf * 16 + lrow;
                int chunk = ks * 2 + lsel;
                uint32_t addr = stA + a_off(row, chunk);
                LDSM_X4(ah[mf][0], ah[mf][1], ah[mf][2], ah[mf][3], addr);
                LDSM_X4(al[mf][0], al[mf][1], al[mf][2], al[mf][3], addr + 8192);
            }
#pragma unroll
            for (int nj = 0; nj < 4; nj++) {
                int brow = ks * 16 + lrow;
                int bchunk = wn * 8 + nj * 2 + lsel;
                uint32_t baddr = stB + b_off(brow, bchunk);
                uint32_t bh[4], bl[4];
                LDSM_X4_T(bh[0], bh[1], bh[2], bh[3], baddr);
                LDSM_X4_T(bl[0], bl[1], bl[2], bl[3], baddr + 8192);
                // term-major: each acc frag touched once per 4-MMA group
                MMA_BF16(acc[0][2 * nj],     ah[0], bh[0], bh[1]);
                MMA_BF16(acc[1][2 * nj],     ah[1], bh[0], bh[1]);
                MMA_BF16(acc[0][2 * nj + 1], ah[0], bh[2], bh[3]);
                MMA_BF16(acc[1][2 * nj + 1], ah[1], bh[2], bh[3]);

                MMA_BF16(acc[0][2 * nj],     ah[0], bl[0], bl[1]);
                MMA_BF16(acc[1][2 * nj],     ah[1], bl[0], bl[1]);
                MMA_BF16(acc[0][2 * nj + 1], ah[0], bl[2], bl[3]);
                MMA_BF16(acc[1][2 * nj + 1], ah[1], bl[2], bl[3]);

                MMA_BF16(acc[0][2 * nj],     al[0], bh[0], bh[1]);
                MMA_BF16(acc[1][2 * nj],     al[1], bh[0], bh[1]);
                MMA_BF16(acc[0][2 * nj + 1], al[0], bh[2], bh[3]);
                MMA_BF16(acc[1][2 * nj + 1], al[1], bh[2], bh[3]);
            }
        }
    }
}

// ---------------------------------------------------------------------------
// Fused QKV GEMM: Out = x @ [wq|wk|wv] + bias over N=2304.
// CTA-x 0..15 -> Q (RoPE+scale*log2e, [B,H,T,D]); 16 -> K (RoPE); 17 -> V.
// ---------------------------------------------------------------------------
__global__ __launch_bounds__(256, 2)
void gemm_qkv(const bf16* __restrict__ Ah, const bf16* __restrict__ Al,
              const bf16* __restrict__ Wh, const bf16* __restrict__ Wl,
              const float* __restrict__ bias,
              bf16* __restrict__ Qh, bf16* __restrict__ Ql,
              bf16* __restrict__ Kh, bf16* __restrict__ Kl,
              bf16* __restrict__ Vh, bf16* __restrict__ Vl,
              const float* __restrict__ cs, const float* __restrict__ sn)
{
    extern __shared__ char sm[];
    const uint32_t sb = smem_u32(sm);
    const int tid  = threadIdx.x;
    const int lane = tid & 31;
    const int wid  = tid >> 5;
    const int wm   = wid >> 1;
    const int wn   = wid & 1;
    const int bxid = blockIdx.x;
    const int m0   = blockIdx.y * 128;
    const int n0   = bxid * 128;

    float acc[2][8][4];
#pragma unroll
    for (int i = 0; i < 2; i++)
#pragma unroll
        for (int j = 0; j < 8; j++)
#pragma unroll
            for (int q = 0; q < 4; q++) acc[i][j][q] = 0.f;

    gemm_mainloop(sb, Ah, Al, Wh, Wl, NQKV, m0, n0, tid, lane, wm, wn, acc);

    const int g = lane >> 2, t = lane & 3;
#pragma unroll
    for (int mf = 0; mf < 2; mf++) {
        int row0 = m0 + wm * 32 + mf * 16 + g;
#pragma unroll
        for (int nt = 0; nt < 8; nt++) {
            int col = n0 + wn * 64 + nt * 8 + 2 * t;
            float2 bi = *(const float2*)(bias + col);
            float a0 = acc[mf][nt][0] + bi.x, a1 = acc[mf][nt][1] + bi.y;
            float a2 = acc[mf][nt][2] + bi.x, a3 = acc[mf][nt][3] + bi.y;
            if (bxid < 16) {
                int f = (col & 127) >> 1;
#pragma unroll
                for (int rr = 0; rr < 2; rr++) {
                    int r = row0 + rr * 8;
                    int tloc = r & (TT - 1);
                    float c = cs[tloc * 64 + f], s = sn[tloc * 64 + f];
                    float re = rr ? a2 : a0, im = rr ? a3 : a1;
                    float ore = (re * c - im * s) * QSCALE;
                    float oim = (re * s + im * c) * QSCALE;
                    uint32_t hi, lo;
                    split2(ore, oim, hi, lo);
                    int bq = r >> 11, hq = col >> 7;
                    size_t idx = ((size_t)(bq * HH + hq) * TT + tloc) * DD + (col & 127);
                    *(uint32_t*)(Qh + idx) = hi;
                    *(uint32_t*)(Ql + idx) = lo;
                }
            } else if (bxid == 16) {
                int colp = col - 2048;
                int f = colp >> 1;
#pragma unroll
                for (int rr = 0; rr < 2; rr++) {
                    int r = row0 + rr * 8;
                    int tloc = r & (TT - 1);
                    float c = cs[tloc * 64 + f], s = sn[tloc * 64 + f];
                    float re = rr ? a2 : a0, im = rr ? a3 : a1;
                    float ore = re * c - im * s;
                    float oim = re * s + im * c;
                    uint32_t hi, lo;
                    split2(ore, oim, hi, lo);
                    size_t idx = (size_t)r * DD + colp;
                    *(uint32_t*)(Kh + idx) = hi;
                    *(uint32_t*)(Kl + idx) = lo;
                }
            } else {
                int colp = col - 2176;
                uint32_t hi, lo;
                split2(a0, a1, hi, lo);
                *(uint32_t*)(Vh + (size_t)row0 * DD + colp) = hi;
                *(uint32_t*)(Vl + (size_t)row0 * DD + colp) = lo;
                split2(a2, a3, hi, lo);
                *(uint32_t*)(Vh + (size_t)(row0 + 8) * DD + colp) = hi;
                *(uint32_t*)(Vl + (size_t)(row0 + 8) * DD + colp) = lo;
            }
        }
    }
}

// ---------------------------------------------------------------------------
// Output GEMM: out = O @ wo + bias (fp32 out, N=2048)
// ---------------------------------------------------------------------------
__global__ __launch_bounds__(256, 2)
void gemm_out(const bf16* __restrict__ Ah, const bf16* __restrict__ Al,
              const bf16* __restrict__ Wh, const bf16* __restrict__ Wl,
              const float* __restrict__ bias, float* __restrict__ OutF)
{
    extern __shared__ char sm[];
    const uint32_t sb = smem_u32(sm);
    const int tid  = threadIdx.x;
    const int lane = tid & 31;
    const int wid  = tid >> 5;
    const int wm   = wid >> 1;
    const int wn   = wid & 1;
    const int m0   = blockIdx.y * 128;
    const int n0   = blockIdx.x * 128;

    float acc[2][8][4];
#pragma unroll
    for (int i = 0; i < 2; i++)
#pragma unroll
        for (int j = 0; j < 8; j++)
#pragma unroll
            for (int q = 0; q < 4; q++) acc[i][j][q] = 0.f;

    gemm_mainloop(sb, Ah, Al, Wh, Wl, CC, m0, n0, tid, lane, wm, wn, acc);

    const int g = lane >> 2, t = lane & 3;
#pragma unroll
    for (int mf = 0; mf < 2; mf++) {
        int row0 = m0 + wm * 32 + mf * 16 + g;
#pragma unroll
        for (int nt = 0; nt < 8; nt++) {
            int col = n0 + wn * 64 + nt * 8 + 2 * t;
            float2 bi = *(const float2*)(bias + col);
            *(float2*)(OutF + (size_t)row0 * CC + col) =
                make_float2(acc[mf][nt][0] + bi.x, acc[mf][nt][1] + bi.y);
            *(float2*)(OutF + (size_t)(row0 + 8) * CC + col) =
                make_float2(acc[mf][nt][2] + bi.x, acc[mf][nt][3] + bi.y);
        }
    }
}

// ---------------------------------------------------------------------------
// Flash attention on mma.sync: BM=64 (4 warps x 16 rows), BN=32, D=128.
// 96KB smem -> 2 CTAs/SM. Softmax in base-2. Term-major MMA ordering.
// ---------------------------------------------------------------------------
#define AQ_L 16384u
#define AKV(s) (32768u + (uint32_t)(s) * 32768u)
#define A_SMEM 98304

__device__ __forceinline__ uint32_t toff(int r, int c) {
    return (uint32_t)(r * 256 + ((c ^ (r & 7)) << 4));
}

__global__ __launch_bounds__(128, 2) void attn_mma(
    const bf16* __restrict__ Qh, const bf16* __restrict__ Ql,
    const bf16* __restrict__ Kh, const bf16* __restrict__ Kl,
    const bf16* __restrict__ Vh, const bf16* __restrict__ Vl,
    bf16* __restrict__ Oh, bf16* __restrict__ Ol)
{
    extern __shared__ char sm[];
    const uint32_t sb = smem_u32(sm);
    const int tid = threadIdx.x, lane = tid & 31, w = tid >> 5;
    const int id = blockIdx.x;
    const int bx = (TT / 64 - 1) - (id >> 5);   // heavy-first
    const int hb = id & 31;
    const int h  = hb & 15;
    const int b  = hb >> 4;
    const int i0 = bx * 64;
    const int jtmax = 2 * bx + 1;               // BN=32 tiles

    const size_t qbase  = ((size_t)(b * HH + h) * TT + i0) * DD;
    const size_t kvbase = (size_t)b * TT * DD;

    // Q tile (64 rows) + KV stage 0 (32 rows)
#pragma unroll
    for (int i = 0; i < 8; i++) {
        int cid = i * 128 + tid;
        int r = cid >> 4, c = cid & 15;
        size_t gs = qbase + (size_t)r * DD + c * 8;
        uint32_t off = toff(r, c);
        CP16(sb + off, Qh + gs);
        CP16(sb + AQ_L + off, Ql + gs);
    }
#pragma unroll
    for (int i = 0; i < 4; i++) {
        int cid = i * 128 + tid;
        int r = cid >> 4, c = cid & 15;
        size_t gs = kvbase + (size_t)r * DD + c * 8;
        uint32_t off = toff(r, c);
        CP16(sb + AKV(0) + off,          Kh + gs);
        CP16(sb + AKV(0) + 8192 + off,   Kl + gs);
        CP16(sb + AKV(0) + 16384 + off,  Vh + gs);
        CP16(sb + AKV(0) + 24576 + off,  Vl + gs);
    }
    CP_COMMIT();

    const int lrA = lane & 15;
    const int lsA = lane >> 4;
    const int lrB = (lane & 7) + ((lane >> 4) << 3);
    const int csB = (lane >> 3) & 1;
    const int g = lane >> 2, t = lane & 3;

    float oa[16][4];
#pragma unroll
    for (int i = 0; i < 16; i++)
#pragma unroll
        for (int j = 0; j < 4; j++) oa[i][j] = 0.f;
    float m0r = -1e30f, m1r = -1e30f, l0r = 0.f, l1r = 0.f;

    for (int jt = 0; jt <= jtmax; jt++) {
        if (jt > 0) __syncthreads();
        if (jt + 1 <= jtmax) {
            uint32_t stg = AKV((jt + 1) & 1);
#pragma unroll
            for (int i = 0; i < 4; i++) {
                int cid = i * 128 + tid;
                int r = cid >> 4, c = cid & 15;
                size_t gs = kvbase + (size_t)((jt + 1) * 32 + r) * DD + c * 8;
                uint32_t off = toff(r, c);
                CP16(sb + stg + off,          Kh + gs);
                CP16(sb + stg + 8192 + off,   Kl + gs);
                CP16(sb + stg + 16384 + off,  Vh + gs);
                CP16(sb + stg + 24576 + off,  Vl + gs);
            }
            CP_COMMIT();
            CP_WAIT(1);
        } else {
            CP_WAIT(0);
        }
        __syncthreads();

        if (32 * jt > i0 + 16 * w + 15) continue;

        const uint32_t kvs = sb + AKV(jt & 1);

        // ---- S = Q K^T (term-major, both np K-frags hoisted) ----
        float sa[4][4];
#pragma unroll
        for (int i = 0; i < 4; i++)
#pragma unroll
            for (int j = 0; j < 4; j++) sa[i][j] = 0.f;

#pragma unroll
        for (int ks = 0; ks < 8; ks++) {
            uint32_t ah[4], al[4];
            uint32_t qaddr = sb + toff(16 * w + lrA, 2 * ks + lsA);
            LDSM_X4(ah[0], ah[1], ah[2], ah[3], qaddr);
            LDSM_X4(al[0], al[1], al[2], al[3], qaddr + AQ_L);

            uint32_t kh[2][4], kl[2][4];
#pragma unroll
            for (int np = 0; np < 2; np++) {
                uint32_t kaddr = kvs + toff(np * 16 + lrB, 2 * ks + csB);
                LDSM_X4(kh[np][0], kh[np][1], kh[np][2], kh[np][3], kaddr);
                LDSM_X4(kl[np][0], kl[np][1], kl[np][2], kl[np][3], kaddr + 8192);
            }
            // term-major: distance 4 per sa frag
            MMA_BF16(sa[0], ah, kh[0][0], kh[0][1]);
            MMA_BF16(sa[1], ah, kh[0][2], kh[0][3]);
            MMA_BF16(sa[2], ah, kh[1][0], kh[1][1]);
            MMA_BF16(sa[3], ah, kh[1][2], kh[1][3]);

            MMA_BF16(sa[0], ah, kl[0][0], kl[0][1]);
            MMA_BF16(sa[1], ah, kl[0][2], kl[0][3]);
            MMA_BF16(sa[2], ah, kl[1][0], kl[1][1]);
            MMA_BF16(sa[3], ah, kl[1][2], kl[1][3]);

            MMA_BF16(sa[0], al, kh[0][0], kh[0][1]);
            MMA_BF16(sa[1], al, kh[0][2], kh[0][3]);
            MMA_BF16(sa[2], al, kh[1][0], kh[1][1]);
            MMA_BF16(sa[3], al, kh[1][2], kh[1][3]);
        }

        // ---- causal mask ----
        if (32 * jt + 31 > i0 + 16 * w) {
            int r0g = i0 + 16 * w + g;
#pragma unroll
            for (int nf = 0; nf < 4; nf++) {
                int cg = 32 * jt + nf * 8 + 2 * t;
                if (cg     > r0g)     sa[nf][0] = -1e30f;
                if (cg + 1 > r0g)     sa[nf][1] = -1e30f;
                if (cg     > r0g + 8) sa[nf][2] = -1e30f;
                if (cg + 1 > r0g + 8) sa[nf][3] = -1e30f;
            }
        }

        // ---- online softmax (base-2) ----
        float mx0 = -1e30f, mx1 = -1e30f;
#pragma unroll
        for (int nf = 0; nf < 4; nf++) {
            mx0 = fmaxf(mx0, fmaxf(sa[nf][0], sa[nf][1]));
            mx1 = fmaxf(mx1, fmaxf(sa[nf][2], sa[nf][3]));
        }
        mx0 = fmaxf(mx0, __shfl_xor_sync(0xffffffffu, mx0, 1));
        mx0 = fmaxf(mx0, __shfl_xor_sync(0xffffffffu, mx0, 2));
        mx1 = fmaxf(mx1, __shfl_xor_sync(0xffffffffu, mx1, 1));
        mx1 = fmaxf(mx1, __shfl_xor_sync(0xffffffffu, mx1, 2));
        float mn0 = fmaxf(m0r, mx0), mn1 = fmaxf(m1r, mx1);

        float sum0 = 0.f, sum1 = 0.f;
#pragma unroll
        for (int nf = 0; nf < 4; nf++) {
            sa[nf][0] = ex2(sa[nf][0] - mn0);
            sa[nf][1] = ex2(sa[nf][1] - mn0);
            sa[nf][2] = ex2(sa[nf][2] - mn1);
            sa[nf][3] = ex2(sa[nf][3] - mn1);
            sum0 += sa[nf][0] + sa[nf][1];
            sum1 += sa[nf][2] + sa[nf][3];
        }
        sum0 += __shfl_xor_sync(0xffffffffu, sum0, 1);
        sum0 += __shfl_xor_sync(0xffffffffu, sum0, 2);
        sum1 += __shfl_xor_sync(0xffffffffu, sum1, 1);
        sum1 += __shfl_xor_sync(0xffffffffu, sum1, 2);

        float scl0 = ex2(m0r - mn0), scl1 = ex2(m1r - mn1);
        l0r = l0r * scl0 + sum0;
        l1r = l1r * scl1 + sum1;
        m0r = mn0; m1r = mn1;

#pragma unroll
        for (int nf = 0; nf < 16; nf++) {
            oa[nf][0] *= scl0; oa[nf][1] *= scl0;
            oa[nf][2] *= scl1; oa[nf][3] *= scl1;
        }

        // ---- O += P V (term-major, V-frags hoisted in np pairs) ----
#pragma unroll
        for (int s = 0; s < 2; s++) {
            uint32_t aPh[4], aPl[4];
            split2(sa[2 * s][0],     sa[2 * s][1],     aPh[0], aPl[0]);
            split2(sa[2 * s][2],     sa[2 * s][3],     aPh[1], aPl[1]);
            split2(sa[2 * s + 1][0], sa[2 * s + 1][1], aPh[2], aPl[2]);
            split2(sa[2 * s + 1][2], sa[2 * s + 1][3], aPh[3], aPl[3]);
#pragma unroll
            for (int npp = 0; npp < 4; npp++) {
                int np0 = 2 * npp, np1 = 2 * npp + 1;
                uint32_t va0 = kvs + 16384 + toff(s * 16 + lrA, 2 * np0 + lsA);
                uint32_t va1 = kvs + 16384 + toff(s * 16 + lrA, 2 * np1 + lsA);
                uint32_t vh0[4], vl0[4], vh1[4], vl1[4];
                LDSM_X4_T(vh0[0], vh0[1], vh0[2], vh0[3], va0);
                LDSM_X4_T(vl0[0], vl0[1], vl0[2], vl0[3], va0 + 8192);
                LDSM_X4_T(vh1[0], vh1[1], vh1[2], vh1[3], va1);
                LDSM_X4_T(vl1[0], vl1[1], vl1[2], vl1[3], va1 + 8192);

                MMA_BF16(oa[2 * np0],     aPh, vh0[0], vh0[1]);
                MMA_BF16(oa[2 * np0 + 1], aPh, vh0[2], vh0[3]);
                MMA_BF16(oa[2 * np1],     aPh, vh1[0], vh1[1]);
                MMA_BF16(oa[2 * np1 + 1], aPh, vh1[2], vh1[3]);

                MMA_BF16(oa[2 * np0],     aPh, vl0[0], vl0[1]);
                MMA_BF16(oa[2 * np0 + 1], aPh, vl0[2], vl0[3]);
                MMA_BF16(oa[2 * np1],     aPh, vl1[0], vl1[1]);
                MMA_BF16(oa[2 * np1 + 1], aPh, vl1[2], vl1[3]);

                MMA_BF16(oa[2 * np0],     aPl, vh0[0], vh0[1]);
                MMA_BF16(oa[2 * np0 + 1], aPl, vh0[2], vh0[3]);
                MMA_BF16(oa[2 * np1],     aPl, vh1[0], vh1[1]);
                MMA_BF16(oa[2 * np1 + 1], aPl, vh1[2], vh1[3]);
            }
        }
    }

    // ---- epilogue ----
    float inv0 = 1.f / l0r, inv1 = 1.f / l1r;
    size_t or0 = (size_t)(b * TT + i0 + 16 * w + g) * CC + h * DD;
    size_t or1 = or0 + (size_t)8 * CC;
#pragma unroll
    for (int nf = 0; nf < 16; nf++) {
        int col = nf * 8 + 2 * t;
        uint32_t hi, lo;
        split2(oa[nf][0] * inv0, oa[nf][1] * inv0, hi, lo);
        *(uint32_t*)(Oh + or0 + col) = hi;
        *(uint32_t*)(Ol + or0 + col) = lo;
        split2(oa[nf][2] * inv1, oa[nf][3] * inv1, hi, lo);
        *(uint32_t*)(Oh + or1 + col) = hi;
        *(uint32_t*)(Ol + or1 + col) = lo;
    }
}

// ---------------------------------------------------------------------------
// Launcher
// ---------------------------------------------------------------------------
extern "C" void kernel_launch(void* const* d_in, const int* in_sizes, int n_in,
                              void* d_out, int out_size)
{
    const float* x    = (const float*)d_in[0];
    const float* fcos = (const float*)d_in[1];
    const float* fsin = (const float*)d_in[2];
    const float* wq   = (const float*)d_in[4];
    const float* wqb  = (const float*)d_in[5];
    const float* wk   = (const float*)d_in[6];
    const float* wkb  = (const float*)d_in[7];
    const float* wv   = (const float*)d_in[8];
    const float* wvb  = (const float*)d_in[9];
    const float* wo   = (const float*)d_in[10];
    const float* wob  = (const float*)d_in[11];
    float* out = (float*)d_out;

    bf16 *xh, *xl, *wh, *wl, *woh, *wol;
    bf16 *Qhp, *Qlp, *Khp, *Klp, *Vhp, *Vlp, *Ohp, *Olp;
    float* biasp;
    cudaGetSymbolAddress((void**)&xh, g_xh);   cudaGetSymbolAddress((void**)&xl, g_xl);
    cudaGetSymbolAddress((void**)&wh, g_wh);   cudaGetSymbolAddress((void**)&wl, g_wl);
    cudaGetSymbolAddress((void**)&woh, g_woh); cudaGetSymbolAddress((void**)&wol, g_wol);
    cudaGetSymbolAddress((void**)&biasp, g_bias);
    cudaGetSymbolAddress((void**)&Qhp, g_Qh);  cudaGetSymbolAddress((void**)&Qlp, g_Ql);
    cudaGetSymbolAddress((void**)&Khp, g_Kh);  cudaGetSymbolAddress((void**)&Klp, g_Kl);
    cudaGetSymbolAddress((void**)&Vhp, g_Vh);  cudaGetSymbolAddress((void**)&Vlp, g_Vl);
    cudaGetSymbolAddress((void**)&Ohp, g_Oh);  cudaGetSymbolAddress((void**)&Olp, g_Ol);

    cudaFuncSetAttribute(gemm_qkv, cudaFuncAttributeMaxDynamicSharedMemorySize, G2SMEM);
    cudaFuncSetAttribute(gemm_out, cudaFuncAttributeMaxDynamicSharedMemorySize, G2SMEM);
    cudaFuncSetAttribute(attn_mma, cudaFuncAttributeMaxDynamicSharedMemorySize, A_SMEM);

    // 1. single merged prep launch
    prep_kernel<<<16905, 256>>>(x, wq, wk, wv, wo, wqb, wkb, wvb,
                                xh, xl, wh, wl, woh, wol, biasp);

    // 2. fused QKV projection
    gemm_qkv<<<dim3(NQKV / 128, MTOT / 128), 256, G2SMEM>>>(
        xh, xl, wh, wl, biasp, Qhp, Qlp, Khp, Klp, Vhp, Vlp, fcos, fsin);

    // 3. flash attention (BM=64, 2 CTAs/SM, heavy-first)
    attn_mma<<<1024, 128, A_SMEM>>>(Qhp, Qlp, Khp, Klp, Vhp, Vlp, Ohp, Olp);

    // 4. output projection -> d_out
    gemm_out<<<dim3(CC / 128, MTOT / 128), 256, G2SMEM>>>(
        Ohp, Olp, woh, wol, wob, out);
}

// round 9
// speedup vs baseline: 1.0242x; 1.0242x over previous
#include <cuda_runtime.h>
#include <cuda_bf16.h>
#include <cstdint>

#define BB 2
#define TT 2048
#define CC 2048
#define HH 16
#define DD 128
#define MTOT (BB * TT)   // 4096
#define KTOT CC          // all GEMMs have K = 2048
#define NQKV 2304        // fused QKV output width: 2048 + 128 + 128
// 1/sqrt(128) * log2(e): softmax done in base-2
#define QSCALE (0.08838834764831845f * 1.44269504088896340f)

typedef __nv_bfloat16 bf16;

// ---------------------------------------------------------------------------
// Scratch (allocation-free: __device__ globals)
// ---------------------------------------------------------------------------
__device__ bf16 g_xh[(size_t)MTOT * CC],  g_xl[(size_t)MTOT * CC];
__device__ bf16 g_wh[(size_t)KTOT * NQKV], g_wl[(size_t)KTOT * NQKV];  // packed QKV W
__device__ bf16 g_woh[(size_t)CC * CC],   g_wol[(size_t)CC * CC];
__device__ float g_bias[NQKV];

__device__ bf16 g_Qh[(size_t)MTOT * CC],  g_Ql[(size_t)MTOT * CC];  // [B,H,T,D]
__device__ bf16 g_Kh[(size_t)MTOT * DD],  g_Kl[(size_t)MTOT * DD];  // [B,T,D]
__device__ bf16 g_Vh[(size_t)MTOT * DD],  g_Vl[(size_t)MTOT * DD];  // [B,T,D]
__device__ bf16 g_Oh[(size_t)MTOT * CC],  g_Ol[(size_t)MTOT * CC];  // [B,T,H*D]

// ---------------------------------------------------------------------------
// PTX helpers
// ---------------------------------------------------------------------------
__device__ __forceinline__ uint32_t smem_u32(const void* p) {
    uint32_t a;
    asm("{ .reg .u64 t; cvta.to.shared.u64 t, %1; cvt.u32.u64 %0, t; }"
        : "=r"(a) : "l"(p));
    return a;
}
__device__ __forceinline__ float ex2(float x) {
    float y;
    asm("ex2.approx.ftz.f32 %0, %1;" : "=f"(y) : "f"(x));
    return y;
}

#define LDSM_X4(r0, r1, r2, r3, addr) \
    asm volatile("ldmatrix.sync.aligned.m8n8.x4.shared.b16 {%0,%1,%2,%3}, [%4];" \
                 : "=r"(r0), "=r"(r1), "=r"(r2), "=r"(r3) : "r"(addr))
#define LDSM_X4_T(r0, r1, r2, r3, addr) \
    asm volatile("ldmatrix.sync.aligned.m8n8.x4.trans.shared.b16 {%0,%1,%2,%3}, [%4];" \
                 : "=r"(r0), "=r"(r1), "=r"(r2), "=r"(r3) : "r"(addr))

#define MMA_BF16(d, a, b0v, b1v) \
    asm volatile("mma.sync.aligned.m16n8k16.row.col.f32.bf16.bf16.f32 " \
                 "{%0,%1,%2,%3}, {%4,%5,%6,%7}, {%8,%9}, {%0,%1,%2,%3};" \
                 : "+f"((d)[0]), "+f"((d)[1]), "+f"((d)[2]), "+f"((d)[3]) \
                 : "r"((a)[0]), "r"((a)[1]), "r"((a)[2]), "r"((a)[3]), \
                   "r"(b0v), "r"(b1v))

#define CP16(dst, src) \
    asm volatile("cp.async.cg.shared.global [%0], [%1], 16;" :: "r"(dst), "l"(src))
#define CP_COMMIT() asm volatile("cp.async.commit_group;" ::: "memory")
#define CP_WAIT(n)  asm volatile("cp.async.wait_group %0;" :: "n"(n) : "memory")

__device__ __forceinline__ uint32_t pack_bf2(bf16 a, bf16 b) {
    return ((uint32_t)__bfloat16_as_ushort(b) << 16) | (uint32_t)__bfloat16_as_ushort(a);
}
__device__ __forceinline__ void split2(float x, float y, uint32_t& hi, uint32_t& lo) {
    bf16 hx = __float2bfloat16(x), hy = __float2bfloat16(y);
    hi = pack_bf2(hx, hy);
    lo = pack_bf2(__float2bfloat16(x - __bfloat162float(hx)),
                  __float2bfloat16(y - __bfloat162float(hy)));
}

// ---------------------------------------------------------------------------
// One merged prep kernel: all fp32->bf16 hi/lo splits + bias pack.
// ---------------------------------------------------------------------------
__global__ __launch_bounds__(256) void prep_kernel(
    const float* __restrict__ x,  const float* __restrict__ wq,
    const float* __restrict__ wk, const float* __restrict__ wv,
    const float* __restrict__ wo,
    const float* __restrict__ qb, const float* __restrict__ kb,
    const float* __restrict__ vb,
    bf16* __restrict__ xh, bf16* __restrict__ xl,
    bf16* __restrict__ wh, bf16* __restrict__ wl,
    bf16* __restrict__ woh, bf16* __restrict__ wol,
    float* __restrict__ bias)
{
    int blk = blockIdx.x;
    int tid = threadIdx.x;
    if (blk < 8192) {                     // x: contiguous
        int i = blk * 256 + tid;
        float4 v = ((const float4*)x)[i];
        uint32_t h0, l0, h1, l1;
        split2(v.x, v.y, h0, l0);
        split2(v.z, v.w, h1, l1);
        ((uint2*)xh)[i] = make_uint2(h0, h1);
        ((uint2*)xl)[i] = make_uint2(l0, l1);
    } else if (blk < 12288) {             // wq -> cols 0..2047
        int i = (blk - 8192) * 256 + tid;
        int row = i >> 9, col = (i << 2) & 2047;
        float4 v = ((const float4*)wq)[i];
        uint32_t h0, l0, h1, l1;
        split2(v.x, v.y, h0, l0);
        split2(v.z, v.w, h1, l1);
        size_t o = (size_t)row * NQKV + col;
        *(uint2*)(wh + o) = make_uint2(h0, h1);
        *(uint2*)(wl + o) = make_uint2(l0, l1);
    } else if (blk < 12544) {             // wk -> cols 2048..2175
        int i = (blk - 12288) * 256 + tid;
        int row = i >> 5, col = (i << 2) & 127;
        float4 v = ((const float4*)wk)[i];
        uint32_t h0, l0, h1, l1;
        split2(v.x, v.y, h0, l0);
        split2(v.z, v.w, h1, l1);
        size_t o = (size_t)row * NQKV + 2048 + col;
        *(uint2*)(wh + o) = make_uint2(h0, h1);
        *(uint2*)(wl + o) = make_uint2(l0, l1);
    } else if (blk < 12800) {             // wv -> cols 2176..2303
        int i = (blk - 12544) * 256 + tid;
        int row = i >> 5, col = (i << 2) & 127;
        float4 v = ((const float4*)wv)[i];
        uint32_t h0, l0, h1, l1;
        split2(v.x, v.y, h0, l0);
        split2(v.z, v.w, h1, l1);
        size_t o = (size_t)row * NQKV + 2176 + col;
        *(uint2*)(wh + o) = make_uint2(h0, h1);
        *(uint2*)(wl + o) = make_uint2(l0, l1);
    } else if (blk < 16896) {             // wo: contiguous
        int i = (blk - 12800) * 256 + tid;
        float4 v = ((const float4*)wo)[i];
        uint32_t h0, l0, h1, l1;
        split2(v.x, v.y, h0, l0);
        split2(v.z, v.w, h1, l1);
        ((uint2*)woh)[i] = make_uint2(h0, h1);
        ((uint2*)wol)[i] = make_uint2(l0, l1);
    } else {                              // bias pack
        int i = (blk - 16896) * 256 + tid;
        if (i < 2048)      bias[i] = qb[i];
        else if (i < 2176) bias[i] = kb[i - 2048];
        else if (i < 2304) bias[i] = vb[i - 2176];
    }
}

// ---------------------------------------------------------------------------
// GEMM machinery: BM=128 BN=128 BK=32, 128 threads (4 warps, 2x2 grid of
// 64x64 warp tiles -> 33% less LDSM traffic/output), cp.async 3-stage.
// ---------------------------------------------------------------------------
#define STG_BYTES 32768
#define G2SMEM (3 * STG_BYTES)
#define NITER (KTOT / 32)   // 64
#define GTHR 128

__device__ __forceinline__ uint32_t a_off(int r, int c) {
    return (uint32_t)(r * 64 + ((c ^ ((r >> 1) & 3)) << 4));
}
__device__ __forceinline__ uint32_t b_off(int r, int c) {
    return (uint32_t)(r * 256 + ((c ^ (r & 7)) << 4));
}

__device__ __forceinline__ void g2s_issue(
    uint32_t stg, const bf16* __restrict__ Ah, const bf16* __restrict__ Al,
    const bf16* __restrict__ Wh, const bf16* __restrict__ Wl,
    int N, int m0, int n0, int k0, int tid)
{
#pragma unroll
    for (int p = 0; p < 4; p++) {
        int cid = p * GTHR + tid;
        int r = cid >> 2, c = cid & 3;
        size_t gs = (size_t)(m0 + r) * KTOT + k0 + c * 8;
        uint32_t off = a_off(r, c);
        CP16(stg + off, Ah + gs);
        CP16(stg + 8192 + off, Al + gs);
    }
#pragma unroll
    for (int p = 0; p < 4; p++) {
        int cid = p * GTHR + tid;
        int r = cid >> 4, c = cid & 15;
        size_t gs = (size_t)(k0 + r) * N + n0 + c * 8;
        uint32_t off = b_off(r, c);
        CP16(stg + 16384 + off, Wh + gs);
        CP16(stg + 24576 + off, Wl + gs);
    }
}

// Mainloop: 64x64 warp tile, 4 m-frags x 8 n-frags, 3-term bf16.
__device__ __forceinline__ void gemm_mainloop(
    uint32_t sb, const bf16* Ah, const bf16* Al, const bf16* Wh, const bf16* Wl,
    int N, int m0, int n0, int tid, int lane, int wm, int wn, float acc[4][8][4])
{
    const int lrow = lane & 15;
    const int lsel = lane >> 4;

    g2s_issue(sb, Ah, Al, Wh, Wl, N, m0, n0, 0, tid);
    CP_COMMIT();
    g2s_issue(sb + STG_BYTES, Ah, Al, Wh, Wl, N, m0, n0, 32, tid);
    CP_COMMIT();

    for (int it = 0; it < NITER; it++) {
        if (it == NITER - 1) CP_WAIT(0); else CP_WAIT(1);
        __syncthreads();
        if (it + 2 < NITER) {
            g2s_issue(sb + ((it + 2) % 3) * STG_BYTES, Ah, Al, Wh, Wl, N,
                      m0, n0, (it + 2) * 32, tid);
            CP_COMMIT();
        }

        const uint32_t stA = sb + (uint32_t)(it % 3) * STG_BYTES;
        const uint32_t stB = stA + 16384;

#pragma unroll
        for (int ks = 0; ks < 2; ks++) {
            uint32_t ah[4][4], al[4][4];
#pragma unroll
            for (int mf = 0; mf < 4; mf++) {
                int row = wm * 64 + mf * 16 + lrow;
                int chunk = ks * 2 + lsel;
                uint32_t addr = stA + a_off(row, chunk);
                LDSM_X4(ah[mf][0], ah[mf][1], ah[mf][2], ah[mf][3], addr);
                LDSM_X4(al[mf][0], al[mf][1], al[mf][2], al[mf][3], addr + 8192);
            }
#pragma unroll
            for (int nj = 0; nj < 4; nj++) {
                int brow = ks * 16 + lrow;
                int bchunk = wn * 8 + nj * 2 + lsel;
                uint32_t baddr = stB + b_off(brow, bchunk);
                uint32_t bh[4], bl[4];
                LDSM_X4_T(bh[0], bh[1], bh[2], bh[3], baddr);
                LDSM_X4_T(bl[0], bl[1], bl[2], bl[3], baddr + 8192);
#pragma unroll
                for (int mf = 0; mf < 4; mf++) {
                    MMA_BF16(acc[mf][2 * nj],     ah[mf], bh[0], bh[1]);
                    MMA_BF16(acc[mf][2 * nj + 1], ah[mf], bh[2], bh[3]);
                }
#pragma unroll
                for (int mf = 0; mf < 4; mf++) {
                    MMA_BF16(acc[mf][2 * nj],     ah[mf], bl[0], bl[1]);
                    MMA_BF16(acc[mf][2 * nj + 1], ah[mf], bl[2], bl[3]);
                }
#pragma unroll
                for (int mf = 0; mf < 4; mf++) {
                    MMA_BF16(acc[mf][2 * nj],     al[mf], bh[0], bh[1]);
                    MMA_BF16(acc[mf][2 * nj + 1], al[mf], bh[2], bh[3]);
                }
            }
        }
    }
}

// ---------------------------------------------------------------------------
// Fused QKV GEMM: Out = x @ [wq|wk|wv] + bias over N=2304.
// CTA-x 0..15 -> Q (RoPE+scale*log2e, [B,H,T,D]); 16 -> K (RoPE); 17 -> V.
// ---------------------------------------------------------------------------
__global__ __launch_bounds__(GTHR, 2)
void gemm_qkv(const bf16* __restrict__ Ah, const bf16* __restrict__ Al,
              const bf16* __restrict__ Wh, const bf16* __restrict__ Wl,
              const float* __restrict__ bias,
              bf16* __restrict__ Qh, bf16* __restrict__ Ql,
              bf16* __restrict__ Kh, bf16* __restrict__ Kl,
              bf16* __restrict__ Vh, bf16* __restrict__ Vl,
              const float* __restrict__ cs, const float* __restrict__ sn)
{
    extern __shared__ char sm[];
    const uint32_t sb = smem_u32(sm);
    const int tid  = threadIdx.x;
    const int lane = tid & 31;
    const int wid  = tid >> 5;
    const int wm   = wid >> 1;
    const int wn   = wid & 1;
    const int bxid = blockIdx.x;
    const int m0   = blockIdx.y * 128;
    const int n0   = bxid * 128;

    float acc[4][8][4];
#pragma unroll
    for (int i = 0; i < 4; i++)
#pragma unroll
        for (int j = 0; j < 8; j++)
#pragma unroll
            for (int q = 0; q < 4; q++) acc[i][j][q] = 0.f;

    gemm_mainloop(sb, Ah, Al, Wh, Wl, NQKV, m0, n0, tid, lane, wm, wn, acc);

    const int g = lane >> 2, t = lane & 3;
#pragma unroll
    for (int mf = 0; mf < 4; mf++) {
        int row0 = m0 + wm * 64 + mf * 16 + g;
#pragma unroll
        for (int nt = 0; nt < 8; nt++) {
            int col = n0 + wn * 64 + nt * 8 + 2 * t;
            float2 bi = *(const float2*)(bias + col);
            float a0 = acc[mf][nt][0] + bi.x, a1 = acc[mf][nt][1] + bi.y;
            float a2 = acc[mf][nt][2] + bi.x, a3 = acc[mf][nt][3] + bi.y;
            if (bxid < 16) {
                int f = (col & 127) >> 1;
#pragma unroll
                for (int rr = 0; rr < 2; rr++) {
                    int r = row0 + rr * 8;
                    int tloc = r & (TT - 1);
                    float c = cs[tloc * 64 + f], s = sn[tloc * 64 + f];
                    float re = rr ? a2 : a0, im = rr ? a3 : a1;
                    float ore = (re * c - im * s) * QSCALE;
                    float oim = (re * s + im * c) * QSCALE;
                    uint32_t hi, lo;
                    split2(ore, oim, hi, lo);
                    int bq = r >> 11, hq = col >> 7;
                    size_t idx = ((size_t)(bq * HH + hq) * TT + tloc) * DD + (col & 127);
                    *(uint32_t*)(Qh + idx) = hi;
                    *(uint32_t*)(Ql + idx) = lo;
                }
            } else if (bxid == 16) {
                int colp = col - 2048;
                int f = colp >> 1;
#pragma unroll
                for (int rr = 0; rr < 2; rr++) {
                    int r = row0 + rr * 8;
                    int tloc = r & (TT - 1);
                    float c = cs[tloc * 64 + f], s = sn[tloc * 64 + f];
                    float re = rr ? a2 : a0, im = rr ? a3 : a1;
                    float ore = re * c - im * s;
                    float oim = re * s + im * c;
                    uint32_t hi, lo;
                    split2(ore, oim, hi, lo);
                    size_t idx = (size_t)r * DD + colp;
                    *(uint32_t*)(Kh + idx) = hi;
                    *(uint32_t*)(Kl + idx) = lo;
                }
            } else {
                int colp = col - 2176;
                uint32_t hi, lo;
                split2(a0, a1, hi, lo);
                *(uint32_t*)(Vh + (size_t)row0 * DD + colp) = hi;
                *(uint32_t*)(Vl + (size_t)row0 * DD + colp) = lo;
                split2(a2, a3, hi, lo);
                *(uint32_t*)(Vh + (size_t)(row0 + 8) * DD + colp) = hi;
                *(uint32_t*)(Vl + (size_t)(row0 + 8) * DD + colp) = lo;
            }
        }
    }
}

// ---------------------------------------------------------------------------
// Output GEMM: out = O @ wo + bias (fp32 out, N=2048)
// ---------------------------------------------------------------------------
__global__ __launch_bounds__(GTHR, 2)
void gemm_out(const bf16* __restrict__ Ah, const bf16* __restrict__ Al,
              const bf16* __restrict__ Wh, const bf16* __restrict__ Wl,
              const float* __restrict__ bias, float* __restrict__ OutF)
{
    extern __shared__ char sm[];
    const uint32_t sb = smem_u32(sm);
    const int tid  = threadIdx.x;
    const int lane = tid & 31;
    const int wid  = tid >> 5;
    const int wm   = wid >> 1;
    const int wn   = wid & 1;
    const int m0   = blockIdx.y * 128;
    const int n0   = blockIdx.x * 128;

    float acc[4][8][4];
#pragma unroll
    for (int i = 0; i < 4; i++)
#pragma unroll
        for (int j = 0; j < 8; j++)
#pragma unroll
            for (int q = 0; q < 4; q++) acc[i][j][q] = 0.f;

    gemm_mainloop(sb, Ah, Al, Wh, Wl, CC, m0, n0, tid, lane, wm, wn, acc);

    const int g = lane >> 2, t = lane & 3;
#pragma unroll
    for (int mf = 0; mf < 4; mf++) {
        int row0 = m0 + wm * 64 + mf * 16 + g;
#pragma unroll
        for (int nt = 0; nt < 8; nt++) {
            int col = n0 + wn * 64 + nt * 8 + 2 * t;
            float2 bi = *(const float2*)(bias + col);
            *(float2*)(OutF + (size_t)row0 * CC + col) =
                make_float2(acc[mf][nt][0] + bi.x, acc[mf][nt][1] + bi.y);
            *(float2*)(OutF + (size_t)(row0 + 8) * CC + col) =
                make_float2(acc[mf][nt][2] + bi.x, acc[mf][nt][3] + bi.y);
        }
    }
}

// ---------------------------------------------------------------------------
// Flash attention on mma.sync: BM=64 (4 warps x 16 rows), BN=32, D=128.
// 96KB smem -> 2 CTAs/SM. Softmax in base-2.
// ---------------------------------------------------------------------------
#define AQ_L 16384u
#define AKV(s) (32768u + (uint32_t)(s) * 32768u)
#define A_SMEM 98304

__device__ __forceinline__ uint32_t toff(int r, int c) {
    return (uint32_t)(r * 256 + ((c ^ (r & 7)) << 4));
}

__global__ __launch_bounds__(128, 2) void attn_mma(
    const bf16* __restrict__ Qh, const bf16* __restrict__ Ql,
    const bf16* __restrict__ Kh, const bf16* __restrict__ Kl,
    const bf16* __restrict__ Vh, const bf16* __restrict__ Vl,
    bf16* __restrict__ Oh, bf16* __restrict__ Ol)
{
    extern __shared__ char sm[];
    const uint32_t sb = smem_u32(sm);
    const int tid = threadIdx.x, lane = tid & 31, w = tid >> 5;
    const int id = blockIdx.x;
    const int bx = (TT / 64 - 1) - (id >> 5);   // heavy-first
    const int hb = id & 31;
    const int h  = hb & 15;
    const int b  = hb >> 4;
    const int i0 = bx * 64;
    const int jtmax = 2 * bx + 1;               // BN=32 tiles

    const size_t qbase  = ((size_t)(b * HH + h) * TT + i0) * DD;
    const size_t kvbase = (size_t)b * TT * DD;

    // Q tile (64 rows) + KV stage 0 (32 rows)
#pragma unroll
    for (int i = 0; i < 8; i++) {
        int cid = i * 128 + tid;
        int r = cid >> 4, c = cid & 15;
        size_t gs = qbase + (size_t)r * DD + c * 8;
        uint32_t off = toff(r, c);
        CP16(sb + off, Qh + gs);
        CP16(sb + AQ_L + off, Ql + gs);
    }
#pragma unroll
    for (int i = 0; i < 4; i++) {
        int cid = i * 128 + tid;
        int r = cid >> 4, c = cid & 15;
        size_t gs = kvbase + (size_t)r * DD + c * 8;
        uint32_t off = toff(r, c);
        CP16(sb + AKV(0) + off,          Kh + gs);
        CP16(sb + AKV(0) + 8192 + off,   Kl + gs);
        CP16(sb + AKV(0) + 16384 + off,  Vh + gs);
        CP16(sb + AKV(0) + 24576 + off,  Vl + gs);
    }
    CP_COMMIT();

    const int lrA = lane & 15;
    const int lsA = lane >> 4;
    const int lrB = (lane & 7) + ((lane >> 4) << 3);
    const int csB = (lane >> 3) & 1;
    const int g = lane >> 2, t = lane & 3;

    float oa[16][4];
#pragma unroll
    for (int i = 0; i < 16; i++)
#pragma unroll
        for (int j = 0; j < 4; j++) oa[i][j] = 0.f;
    float m0r = -1e30f, m1r = -1e30f, l0r = 0.f, l1r = 0.f;

    for (int jt = 0; jt <= jtmax; jt++) {
        if (jt > 0) __syncthreads();
        if (jt + 1 <= jtmax) {
            uint32_t stg = AKV((jt + 1) & 1);
#pragma unroll
            for (int i = 0; i < 4; i++) {
                int cid = i * 128 + tid;
                int r = cid >> 4, c = cid & 15;
                size_t gs = kvbase + (size_t)((jt + 1) * 32 + r) * DD + c * 8;
                uint32_t off = toff(r, c);
                CP16(sb + stg + off,          Kh + gs);
                CP16(sb + stg + 8192 + off,   Kl + gs);
                CP16(sb + stg + 16384 + off,  Vh + gs);
                CP16(sb + stg + 24576 + off,  Vl + gs);
            }
            CP_COMMIT();
            CP_WAIT(1);
        } else {
            CP_WAIT(0);
        }
        __syncthreads();

        if (32 * jt > i0 + 16 * w + 15) continue;

        const uint32_t kvs = sb + AKV(jt & 1);

        // ---- S = Q K^T ----
        float sa[4][4];
#pragma unroll
        for (int i = 0; i < 4; i++)
#pragma unroll
            for (int j = 0; j < 4; j++) sa[i][j] = 0.f;

#pragma unroll
        for (int ks = 0; ks < 8; ks++) {
            uint32_t ah[4], al[4];
            uint32_t qaddr = sb + toff(16 * w + lrA, 2 * ks + lsA);
            LDSM_X4(ah[0], ah[1], ah[2], ah[3], qaddr);
            LDSM_X4(al[0], al[1], al[2], al[3], qaddr + AQ_L);

            uint32_t kh[2][4], kl[2][4];
#pragma unroll
            for (int np = 0; np < 2; np++) {
                uint32_t kaddr = kvs + toff(np * 16 + lrB, 2 * ks + csB);
                LDSM_X4(kh[np][0], kh[np][1], kh[np][2], kh[np][3], kaddr);
                LDSM_X4(kl[np][0], kl[np][1], kl[np][2], kl[np][3], kaddr + 8192);
            }
            MMA_BF16(sa[0], ah, kh[0][0], kh[0][1]);
            MMA_BF16(sa[1], ah, kh[0][2], kh[0][3]);
            MMA_BF16(sa[2], ah, kh[1][0], kh[1][1]);
            MMA_BF16(sa[3], ah, kh[1][2], kh[1][3]);

            MMA_BF16(sa[0], ah, kl[0][0], kl[0][1]);
            MMA_BF16(sa[1], ah, kl[0][2], kl[0][3]);
            MMA_BF16(sa[2], ah, kl[1][0], kl[1][1]);
            MMA_BF16(sa[3], ah, kl[1][2], kl[1][3]);

            MMA_BF16(sa[0], al, kh[0][0], kh[0][1]);
            MMA_BF16(sa[1], al, kh[0][2], kh[0][3]);
            MMA_BF16(sa[2], al, kh[1][0], kh[1][1]);
            MMA_BF16(sa[3], al, kh[1][2], kh[1][3]);
        }

        // ---- causal mask ----
        if (32 * jt + 31 > i0 + 16 * w) {
            int r0g = i0 + 16 * w + g;
#pragma unroll
            for (int nf = 0; nf < 4; nf++) {
                int cg = 32 * jt + nf * 8 + 2 * t;
                if (cg     > r0g)     sa[nf][0] = -1e30f;
                if (cg + 1 > r0g)     sa[nf][1] = -1e30f;
                if (cg     > r0g + 8) sa[nf][2] = -1e30f;
                if (cg + 1 > r0g + 8) sa[nf][3] = -1e30f;
            }
        }

        // ---- online softmax (base-2) ----
        float mx0 = -1e30f, mx1 = -1e30f;
#pragma unroll
        for (int nf = 0; nf < 4; nf++) {
            mx0 = fmaxf(mx0, fmaxf(sa[nf][0], sa[nf][1]));
            mx1 = fmaxf(mx1, fmaxf(sa[nf][2], sa[nf][3]));
        }
        mx0 = fmaxf(mx0, __shfl_xor_sync(0xffffffffu, mx0, 1));
        mx0 = fmaxf(mx0, __shfl_xor_sync(0xffffffffu, mx0, 2));
        mx1 = fmaxf(mx1, __shfl_xor_sync(0xffffffffu, mx1, 1));
        mx1 = fmaxf(mx1, __shfl_xor_sync(0xffffffffu, mx1, 2));
        float mn0 = fmaxf(m0r, mx0), mn1 = fmaxf(m1r, mx1);

        float sum0 = 0.f, sum1 = 0.f;
#pragma unroll
        for (int nf = 0; nf < 4; nf++) {
            sa[nf][0] = ex2(sa[nf][0] - mn0);
            sa[nf][1] = ex2(sa[nf][1] - mn0);
            sa[nf][2] = ex2(sa[nf][2] - mn1);
            sa[nf][3] = ex2(sa[nf][3] - mn1);
            sum0 += sa[nf][0] + sa[nf][1];
            sum1 += sa[nf][2] + sa[nf][3];
        }
        sum0 += __shfl_xor_sync(0xffffffffu, sum0, 1);
        sum0 += __shfl_xor_sync(0xffffffffu, sum0, 2);
        sum1 += __shfl_xor_sync(0xffffffffu, sum1, 1);
        sum1 += __shfl_xor_sync(0xffffffffu, sum1, 2);

        float scl0 = ex2(m0r - mn0), scl1 = ex2(m1r - mn1);
        l0r = l0r * scl0 + sum0;
        l1r = l1r * scl1 + sum1;
        m0r = mn0; m1r = mn1;

#pragma unroll
        for (int nf = 0; nf < 16; nf++) {
            oa[nf][0] *= scl0; oa[nf][1] *= scl0;
            oa[nf][2] *= scl1; oa[nf][3] *= scl1;
        }

        // ---- O += P V ----
#pragma unroll
        for (int s = 0; s < 2; s++) {
            uint32_t aPh[4], aPl[4];
            split2(sa[2 * s][0],     sa[2 * s][1],     aPh[0], aPl[0]);
            split2(sa[2 * s][2],     sa[2 * s][3],     aPh[1], aPl[1]);
            split2(sa[2 * s + 1][0], sa[2 * s + 1][1], aPh[2], aPl[2]);
            split2(sa[2 * s + 1][2], sa[2 * s + 1][3], aPh[3], aPl[3]);
#pragma unroll
            for (int npp = 0; npp < 4; npp++) {
                int np0 = 2 * npp, np1 = 2 * npp + 1;
                uint32_t va0 = kvs + 16384 + toff(s * 16 + lrA, 2 * np0 + lsA);
                uint32_t va1 = kvs + 16384 + toff(s * 16 + lrA, 2 * np1 + lsA);
                uint32_t vh0[4], vl0[4], vh1[4], vl1[4];
                LDSM_X4_T(vh0[0], vh0[1], vh0[2], vh0[3], va0);
                LDSM_X4_T(vl0[0], vl0[1], vl0[2], vl0[3], va0 + 8192);
                LDSM_X4_T(vh1[0], vh1[1], vh1[2], vh1[3], va1);
                LDSM_X4_T(vl1[0], vl1[1], vl1[2], vl1[3], va1 + 8192);

                MMA_BF16(oa[2 * np0],     aPh, vh0[0], vh0[1]);
                MMA_BF16(oa[2 * np0 + 1], aPh, vh0[2], vh0[3]);
                MMA_BF16(oa[2 * np1],     aPh, vh1[0], vh1[1]);
                MMA_BF16(oa[2 * np1 + 1], aPh, vh1[2], vh1[3]);

                MMA_BF16(oa[2 * np0],     aPh, vl0[0], vl0[1]);
                MMA_BF16(oa[2 * np0 + 1], aPh, vl0[2], vl0[3]);
                MMA_BF16(oa[2 * np1],     aPh, vl1[0], vl1[1]);
                MMA_BF16(oa[2 * np1 + 1], aPh, vl1[2], vl1[3]);

                MMA_BF16(oa[2 * np0],     aPl, vh0[0], vh0[1]);
                MMA_BF16(oa[2 * np0 + 1], aPl, vh0[2], vh0[3]);
                MMA_BF16(oa[2 * np1],     aPl, vh1[0], vh1[1]);
                MMA_BF16(oa[2 * np1 + 1], aPl, vh1[2], vh1[3]);
            }
        }
    }

    // ---- epilogue ----
    float inv0 = 1.f / l0r, inv1 = 1.f / l1r;
    size_t or0 = (size_t)(b * TT + i0 + 16 * w + g) * CC + h * DD;
    size_t or1 = or0 + (size_t)8 * CC;
#pragma unroll
    for (int nf = 0; nf < 16; nf++) {
        int col = nf * 8 + 2 * t;
        uint32_t hi, lo;
        split2(oa[nf][0] * inv0, oa[nf][1] * inv0, hi, lo);
        *(uint32_t*)(Oh + or0 + col) = hi;
        *(uint32_t*)(Ol + or0 + col) = lo;
        split2(oa[nf][2] * inv1, oa[nf][3] * inv1, hi, lo);
        *(uint32_t*)(Oh + or1 + col) = hi;
        *(uint32_t*)(Ol + or1 + col) = lo;
    }
}

// ---------------------------------------------------------------------------
// Launcher
// ---------------------------------------------------------------------------
extern "C" void kernel_launch(void* const* d_in, const int* in_sizes, int n_in,
                              void* d_out, int out_size)
{
    const float* x    = (const float*)d_in[0];
    const float* fcos = (const float*)d_in[1];
    const float* fsin = (const float*)d_in[2];
    const float* wq   = (const float*)d_in[4];
    const float* wqb  = (const float*)d_in[5];
    const float* wk   = (const float*)d_in[6];
    const float* wkb  = (const float*)d_in[7];
    const float* wv   = (const float*)d_in[8];
    const float* wvb  = (const float*)d_in[9];
    const float* wo   = (const float*)d_in[10];
    const float* wob  = (const float*)d_in[11];
    float* out = (float*)d_out;

    bf16 *xh, *xl, *wh, *wl, *woh, *wol;
    bf16 *Qhp, *Qlp, *Khp, *Klp, *Vhp, *Vlp, *Ohp, *Olp;
    float* biasp;
    cudaGetSymbolAddress((void**)&xh, g_xh);   cudaGetSymbolAddress((void**)&xl, g_xl);
    cudaGetSymbolAddress((void**)&wh, g_wh);   cudaGetSymbolAddress((void**)&wl, g_wl);
    cudaGetSymbolAddress((void**)&woh, g_woh); cudaGetSymbolAddress((void**)&wol, g_wol);
    cudaGetSymbolAddress((void**)&biasp, g_bias);
    cudaGetSymbolAddress((void**)&Qhp, g_Qh);  cudaGetSymbolAddress((void**)&Qlp, g_Ql);
    cudaGetSymbolAddress((void**)&Khp, g_Kh);  cudaGetSymbolAddress((void**)&Klp, g_Kl);
    cudaGetSymbolAddress((void**)&Vhp, g_Vh);  cudaGetSymbolAddress((void**)&Vlp, g_Vl);
    cudaGetSymbolAddress((void**)&Ohp, g_Oh);  cudaGetSymbolAddress((void**)&Olp, g_Ol);

    cudaFuncSetAttribute(gemm_qkv, cudaFuncAttributeMaxDynamicSharedMemorySize, G2SMEM);
    cudaFuncSetAttribute(gemm_out, cudaFuncAttributeMaxDynamicSharedMemorySize, G2SMEM);
    cudaFuncSetAttribute(attn_mma, cudaFuncAttributeMaxDynamicSharedMemorySize, A_SMEM);

    // 1. single merged prep launch
    prep_kernel<<<16905, 256>>>(x, wq, wk, wv, wo, wqb, wkb, wvb,
                                xh, xl, wh, wl, woh, wol, biasp);

    // 2. fused QKV projection (128-thread CTAs, 64x64 warp tiles)
    gemm_qkv<<<dim3(NQKV / 128, MTOT / 128), GTHR, G2SMEM>>>(
        xh, xl, wh, wl, biasp, Qhp, Qlp, Khp, Klp, Vhp, Vlp, fcos, fsin);

    // 3. flash attention (BM=64, 2 CTAs/SM, heavy-first)
    attn_mma<<<1024, 128, A_SMEM>>>(Qhp, Qlp, Khp, Klp, Vhp, Vlp, Ohp, Olp);

    // 4. output projection -> d_out
    gemm_out<<<dim3(CC / 128, MTOT / 128), GTHR, G2SMEM>>>(
        Ohp, Olp, woh, wol, wob, out);
}